// round 2
// baseline (speedup 1.0000x reference)
#include <cuda_runtime.h>
#include <cstdint>

// TemplatePointwiseAttention — fused fp32 baseline.
// B=1, Nt=4, Nr=512, Ct=64, Cz=128, H=4, d=32.
// One block = 64 pixels, 256 threads, everything fused via shared memory.

#define NR   512
#define NT   4
#define CT   64
#define CZ   128
#define NH   4
#define DH   32
#define PIX  (NR*NR)          // 262144
#define TILE_P 64
#define LDA  132              // padded leading dim for 128-wide tiles
#define LDT  68               // padded leading dim for 64-wide T tiles

// smem layout (floats):
//   sW   : 16384            (weight staging: wq | wk||wv | wo)
//   sQ   : 64*LDA = 8448
//   sA   : 64*LDA = 8448    (Z -> K per template -> O)
//   sT   : 64*LDT = 4352
//   sM, sDen, sWt, sFac : 256 each
//   sBias: 4
//   sBo  : 128
#define SMEM_FLOATS (16384 + 8448 + 8448 + 4352 + 4*256 + 4 + 128)

// Register-tiled GEMM: C[64][128] += A[64][K] * B[K][128].
// Thread (ty,tx) owns rows ty*4..+3, cols tx*8..+7.
template<int K>
__device__ __forceinline__ void gemm_acc(const float* __restrict__ A, int lda,
                                         const float* __restrict__ B,
                                         int ty4, int tx8, float acc[4][8])
{
#pragma unroll 2
    for (int k4 = 0; k4 < K; k4 += 4) {
        float4 av[4];
#pragma unroll
        for (int i = 0; i < 4; i++)
            av[i] = *reinterpret_cast<const float4*>(&A[(ty4 + i) * lda + k4]);
#pragma unroll
        for (int kk = 0; kk < 4; kk++) {
            float4 b0 = *reinterpret_cast<const float4*>(&B[(k4 + kk) * CZ + tx8]);
            float4 b1 = *reinterpret_cast<const float4*>(&B[(k4 + kk) * CZ + tx8 + 4]);
#pragma unroll
            for (int i = 0; i < 4; i++) {
                float a = reinterpret_cast<const float*>(&av[i])[kk];
                acc[i][0] += a * b0.x; acc[i][1] += a * b0.y;
                acc[i][2] += a * b0.z; acc[i][3] += a * b0.w;
                acc[i][4] += a * b1.x; acc[i][5] += a * b1.y;
                acc[i][6] += a * b1.z; acc[i][7] += a * b1.w;
            }
        }
    }
}

__global__ __launch_bounds__(256)
void tpa_fused_kernel(const float* __restrict__ t,
                      const float* __restrict__ z,
                      const float* __restrict__ tmask,
                      const float* __restrict__ wq,
                      const float* __restrict__ wk,
                      const float* __restrict__ wv,
                      const float* __restrict__ wo,
                      const float* __restrict__ bo,
                      float* __restrict__ outp)
{
    extern __shared__ float smem[];
    float* sW    = smem;                  // 16384
    float* sQ    = sW + 16384;            // 8448
    float* sA    = sQ + 64 * LDA;         // 8448
    float* sT    = sA + 64 * LDA;         // 4352
    float* sM    = sT + 64 * LDT;         // 256
    float* sDen  = sM + 256;              // 256
    float* sWt   = sDen + 256;            // 256
    float* sFac  = sWt + 256;             // 256
    float* sBias = sFac + 256;            // 4
    float* sBo   = sBias + 4;             // 128

    const int tid = threadIdx.x;
    const int tx  = tid & 15;
    const int ty  = tid >> 4;
    const int tx8 = tx * 8;
    const int ty4 = ty * 4;
    const int p0  = blockIdx.x * TILE_P;

    // ---- Phase 0: load wq, Z tile, mask bias, bo; init softmax state ----
    {
        const float4* wq4 = reinterpret_cast<const float4*>(wq);
        float4* sW4 = reinterpret_cast<float4*>(sW);
        for (int i = tid; i < 4096; i += 256) sW4[i] = wq4[i];

        const float4* z4 = reinterpret_cast<const float4*>(z);
        for (int i = tid; i < 64 * 32; i += 256) {
            int r = i >> 5, c = i & 31;
            *reinterpret_cast<float4*>(&sA[r * LDA + c * 4]) =
                z4[(size_t)(p0 + r) * 32 + c];
        }
        if (tid < NT) sBias[tid] = 100000.0f * (tmask[tid] - 1.0f);
        if (tid < 32)
            reinterpret_cast<float4*>(sBo)[tid] =
                reinterpret_cast<const float4*>(bo)[tid];
        sM[tid]   = -3.0e38f;
        sDen[tid] = 0.0f;
    }
    __syncthreads();

    // ---- Phase 1: Q = Z @ wq * (1/sqrt(d)) -> sQ ----
    float acc[4][8];
    {
#pragma unroll
        for (int i = 0; i < 4; i++)
#pragma unroll
            for (int j = 0; j < 8; j++) acc[i][j] = 0.0f;
        gemm_acc<CZ>(sA, LDA, sW, ty4, tx8, acc);
        const float qscale = 0.17677669529663687f;  // 1/sqrt(32)
#pragma unroll
        for (int i = 0; i < 4; i++) {
            float4 v0 = make_float4(acc[i][0]*qscale, acc[i][1]*qscale,
                                    acc[i][2]*qscale, acc[i][3]*qscale);
            float4 v1 = make_float4(acc[i][4]*qscale, acc[i][5]*qscale,
                                    acc[i][6]*qscale, acc[i][7]*qscale);
            *reinterpret_cast<float4*>(&sQ[(ty4 + i) * LDA + tx8])     = v0;
            *reinterpret_cast<float4*>(&sQ[(ty4 + i) * LDA + tx8 + 4]) = v1;
        }
    }
    __syncthreads();

    // ---- load wk || wv into sW (wk at 0, wv at 8192) ----
    {
        const float4* wk4 = reinterpret_cast<const float4*>(wk);
        const float4* wv4 = reinterpret_cast<const float4*>(wv);
        float4* sW4 = reinterpret_cast<float4*>(sW);
        for (int i = tid; i < 4096; i += 256)
            sW4[i] = (i < 2048) ? wk4[i] : wv4[i - 2048];
    }

    float o_acc[4][8];
#pragma unroll
    for (int i = 0; i < 4; i++)
#pragma unroll
        for (int j = 0; j < 8; j++) o_acc[i][j] = 0.0f;

    // ---- Phase 2: template loop with online softmax ----
    for (int tt = 0; tt < NT; tt++) {
        __syncthreads();   // guards sT overwrite (and wk/wv visibility on iter 0)
        // load T tile: tp[p, tt, :] = t[tt, p, :]
        {
            const float4* ts = reinterpret_cast<const float4*>(
                t + ((size_t)tt * PIX + p0) * CT);
            for (int i = tid; i < 64 * 16; i += 256) {
                int r = i >> 4, c = i & 15;
                *reinterpret_cast<float4*>(&sT[r * LDT + c * 4]) = ts[r * 16 + c];
            }
        }
        __syncthreads();

        // K_t = T @ wk -> sA
#pragma unroll
        for (int i = 0; i < 4; i++)
#pragma unroll
            for (int j = 0; j < 8; j++) acc[i][j] = 0.0f;
        gemm_acc<CT>(sT, LDT, sW, ty4, tx8, acc);
#pragma unroll
        for (int i = 0; i < 4; i++) {
            *reinterpret_cast<float4*>(&sA[(ty4 + i) * LDA + tx8]) =
                make_float4(acc[i][0], acc[i][1], acc[i][2], acc[i][3]);
            *reinterpret_cast<float4*>(&sA[(ty4 + i) * LDA + tx8 + 4]) =
                make_float4(acc[i][4], acc[i][5], acc[i][6], acc[i][7]);
        }
        __syncthreads();

        // logits + online softmax update: one thread per (pixel, head)
        {
            int p = tid >> 2, h = tid & 3;
            const float* qp = &sQ[p * LDA + h * DH];
            const float* kp = &sA[p * LDA + h * DH];
            float l = 0.0f;
#pragma unroll
            for (int dd = 0; dd < DH; dd += 4) {
                float4 qv = *reinterpret_cast<const float4*>(&qp[dd]);
                float4 kv = *reinterpret_cast<const float4*>(&kp[dd]);
                l += qv.x * kv.x + qv.y * kv.y + qv.z * kv.z + qv.w * kv.w;
            }
            l += sBias[tt];
            float m_old = sM[tid];
            float m_new = fmaxf(m_old, l);
            float fac = __expf(m_old - m_new);
            float w   = __expf(l - m_new);
            sDen[tid] = sDen[tid] * fac + w;
            sM[tid]   = m_new;
            sFac[tid] = fac;
            sWt[tid]  = w;
        }
        __syncthreads();

        // V_t = T @ wv -> registers, fold into o_acc with rescale
#pragma unroll
        for (int i = 0; i < 4; i++)
#pragma unroll
            for (int j = 0; j < 8; j++) acc[i][j] = 0.0f;
        gemm_acc<CT>(sT, LDT, sW + 8192, ty4, tx8, acc);
        {
            int h = tx >> 2;   // all 8 cols of this thread share one head
#pragma unroll
            for (int i = 0; i < 4; i++) {
                float fac = sFac[(ty4 + i) * 4 + h];
                float w   = sWt[(ty4 + i) * 4 + h];
#pragma unroll
                for (int j = 0; j < 8; j++)
                    o_acc[i][j] = o_acc[i][j] * fac + w * acc[i][j];
            }
        }
    }
    __syncthreads();

    // ---- Phase 3: normalize, stage O in sA, load wo, epilogue GEMM ----
    {
        int h = tx >> 2;
#pragma unroll
        for (int i = 0; i < 4; i++) {
            float inv = 1.0f / sDen[(ty4 + i) * 4 + h];
            *reinterpret_cast<float4*>(&sA[(ty4 + i) * LDA + tx8]) =
                make_float4(o_acc[i][0]*inv, o_acc[i][1]*inv,
                            o_acc[i][2]*inv, o_acc[i][3]*inv);
            *reinterpret_cast<float4*>(&sA[(ty4 + i) * LDA + tx8 + 4]) =
                make_float4(o_acc[i][4]*inv, o_acc[i][5]*inv,
                            o_acc[i][6]*inv, o_acc[i][7]*inv);
        }
        const float4* wo4 = reinterpret_cast<const float4*>(wo);
        float4* sW4 = reinterpret_cast<float4*>(sW);
        for (int i = tid; i < 4096; i += 256) sW4[i] = wo4[i];
    }
    __syncthreads();

#pragma unroll
    for (int i = 0; i < 4; i++)
#pragma unroll
        for (int j = 0; j < 8; j++) acc[i][j] = 0.0f;
    gemm_acc<CZ>(sA, LDA, sW, ty4, tx8, acc);

#pragma unroll
    for (int i = 0; i < 4; i++) {
        size_t base = (size_t)(p0 + ty4 + i) * CZ + tx8;
        float4 r0 = make_float4(acc[i][0] + sBo[tx8 + 0], acc[i][1] + sBo[tx8 + 1],
                                acc[i][2] + sBo[tx8 + 2], acc[i][3] + sBo[tx8 + 3]);
        float4 r1 = make_float4(acc[i][4] + sBo[tx8 + 4], acc[i][5] + sBo[tx8 + 5],
                                acc[i][6] + sBo[tx8 + 6], acc[i][7] + sBo[tx8 + 7]);
        *reinterpret_cast<float4*>(&outp[base])     = r0;
        *reinterpret_cast<float4*>(&outp[base + 4]) = r1;
    }
}

extern "C" void kernel_launch(void* const* d_in, const int* in_sizes, int n_in,
                              void* d_out, int out_size)
{
    const float* t     = (const float*)d_in[0];
    const float* z     = (const float*)d_in[1];
    const float* tmask = (const float*)d_in[2];
    const float* wq    = (const float*)d_in[3];
    const float* wk    = (const float*)d_in[4];
    const float* wv    = (const float*)d_in[5];
    const float* wo    = (const float*)d_in[6];
    const float* bo    = (const float*)d_in[7];
    float* outp = (float*)d_out;

    const int smem_bytes = SMEM_FLOATS * (int)sizeof(float);
    cudaFuncSetAttribute(tpa_fused_kernel,
                         cudaFuncAttributeMaxDynamicSharedMemorySize, smem_bytes);

    dim3 grid(PIX / TILE_P);   // 4096 blocks
    dim3 block(256);
    tpa_fused_kernel<<<grid, block, smem_bytes>>>(
        t, z, tmask, wq, wk, wv, wo, bo, outp);
}

// round 3
// speedup vs baseline: 1.0017x; 1.0017x over previous
#include <cuda_runtime.h>
#include <cstdint>

// TemplatePointwiseAttention — fused fp32 baseline.
// B=1, Nt=4, Nr=512, Ct=64, Cz=128, H=4, d=32.
// One block = 64 pixels, 256 threads, everything fused via shared memory.

#define NR   512
#define NT   4
#define CT   64
#define CZ   128
#define NH   4
#define DH   32
#define PIX  (NR*NR)          // 262144
#define TILE_P 64
#define LDA  132              // padded leading dim for 128-wide tiles
#define LDT  68               // padded leading dim for 64-wide T tiles

// smem layout (floats):
//   sW   : 16384            (weight staging: wq | wk||wv | wo)
//   sQ   : 64*LDA = 8448
//   sA   : 64*LDA = 8448    (Z -> K per template -> O)
//   sT   : 64*LDT = 4352
//   sM, sDen, sWt, sFac : 256 each
//   sBias: 4
//   sBo  : 128
#define SMEM_FLOATS (16384 + 8448 + 8448 + 4352 + 4*256 + 4 + 128)

// Register-tiled GEMM: C[64][128] += A[64][K] * B[K][128].
// Thread (ty,tx) owns rows ty*4..+3, cols tx*8..+7.
template<int K>
__device__ __forceinline__ void gemm_acc(const float* __restrict__ A, int lda,
                                         const float* __restrict__ B,
                                         int ty4, int tx8, float acc[4][8])
{
#pragma unroll 2
    for (int k4 = 0; k4 < K; k4 += 4) {
        float4 av[4];
#pragma unroll
        for (int i = 0; i < 4; i++)
            av[i] = *reinterpret_cast<const float4*>(&A[(ty4 + i) * lda + k4]);
#pragma unroll
        for (int kk = 0; kk < 4; kk++) {
            float4 b0 = *reinterpret_cast<const float4*>(&B[(k4 + kk) * CZ + tx8]);
            float4 b1 = *reinterpret_cast<const float4*>(&B[(k4 + kk) * CZ + tx8 + 4]);
#pragma unroll
            for (int i = 0; i < 4; i++) {
                float a = reinterpret_cast<const float*>(&av[i])[kk];
                acc[i][0] += a * b0.x; acc[i][1] += a * b0.y;
                acc[i][2] += a * b0.z; acc[i][3] += a * b0.w;
                acc[i][4] += a * b1.x; acc[i][5] += a * b1.y;
                acc[i][6] += a * b1.z; acc[i][7] += a * b1.w;
            }
        }
    }
}

__global__ __launch_bounds__(256)
void tpa_fused_kernel(const float* __restrict__ t,
                      const float* __restrict__ z,
                      const float* __restrict__ tmask,
                      const float* __restrict__ wq,
                      const float* __restrict__ wk,
                      const float* __restrict__ wv,
                      const float* __restrict__ wo,
                      const float* __restrict__ bo,
                      float* __restrict__ outp)
{
    extern __shared__ float smem[];
    float* sW    = smem;                  // 16384
    float* sQ    = sW + 16384;            // 8448
    float* sA    = sQ + 64 * LDA;         // 8448
    float* sT    = sA + 64 * LDA;         // 4352
    float* sM    = sT + 64 * LDT;         // 256
    float* sDen  = sM + 256;              // 256
    float* sWt   = sDen + 256;            // 256
    float* sFac  = sWt + 256;             // 256
    float* sBias = sFac + 256;            // 4
    float* sBo   = sBias + 4;             // 128

    const int tid = threadIdx.x;
    const int tx  = tid & 15;
    const int ty  = tid >> 4;
    const int tx8 = tx * 8;
    const int ty4 = ty * 4;
    const int p0  = blockIdx.x * TILE_P;

    // ---- Phase 0: load wq, Z tile, mask bias, bo; init softmax state ----
    {
        const float4* wq4 = reinterpret_cast<const float4*>(wq);
        float4* sW4 = reinterpret_cast<float4*>(sW);
        for (int i = tid; i < 4096; i += 256) sW4[i] = wq4[i];

        const float4* z4 = reinterpret_cast<const float4*>(z);
        for (int i = tid; i < 64 * 32; i += 256) {
            int r = i >> 5, c = i & 31;
            *reinterpret_cast<float4*>(&sA[r * LDA + c * 4]) =
                z4[(size_t)(p0 + r) * 32 + c];
        }
        if (tid < NT) sBias[tid] = 100000.0f * (tmask[tid] - 1.0f);
        if (tid < 32)
            reinterpret_cast<float4*>(sBo)[tid] =
                reinterpret_cast<const float4*>(bo)[tid];
        sM[tid]   = -3.0e38f;
        sDen[tid] = 0.0f;
    }
    __syncthreads();

    // ---- Phase 1: Q = Z @ wq * (1/sqrt(d)) -> sQ ----
    float acc[4][8];
    {
#pragma unroll
        for (int i = 0; i < 4; i++)
#pragma unroll
            for (int j = 0; j < 8; j++) acc[i][j] = 0.0f;
        gemm_acc<CZ>(sA, LDA, sW, ty4, tx8, acc);
        const float qscale = 0.17677669529663687f;  // 1/sqrt(32)
#pragma unroll
        for (int i = 0; i < 4; i++) {
            float4 v0 = make_float4(acc[i][0]*qscale, acc[i][1]*qscale,
                                    acc[i][2]*qscale, acc[i][3]*qscale);
            float4 v1 = make_float4(acc[i][4]*qscale, acc[i][5]*qscale,
                                    acc[i][6]*qscale, acc[i][7]*qscale);
            *reinterpret_cast<float4*>(&sQ[(ty4 + i) * LDA + tx8])     = v0;
            *reinterpret_cast<float4*>(&sQ[(ty4 + i) * LDA + tx8 + 4]) = v1;
        }
    }
    __syncthreads();

    // ---- load wk || wv into sW (wk at 0, wv at 8192) ----
    {
        const float4* wk4 = reinterpret_cast<const float4*>(wk);
        const float4* wv4 = reinterpret_cast<const float4*>(wv);
        float4* sW4 = reinterpret_cast<float4*>(sW);
        for (int i = tid; i < 4096; i += 256)
            sW4[i] = (i < 2048) ? wk4[i] : wv4[i - 2048];
    }

    float o_acc[4][8];
#pragma unroll
    for (int i = 0; i < 4; i++)
#pragma unroll
        for (int j = 0; j < 8; j++) o_acc[i][j] = 0.0f;

    // ---- Phase 2: template loop with online softmax ----
    for (int tt = 0; tt < NT; tt++) {
        __syncthreads();   // guards sT overwrite (and wk/wv visibility on iter 0)
        // load T tile: tp[p, tt, :] = t[tt, p, :]
        {
            const float4* ts = reinterpret_cast<const float4*>(
                t + ((size_t)tt * PIX + p0) * CT);
            for (int i = tid; i < 64 * 16; i += 256) {
                int r = i >> 4, c = i & 15;
                *reinterpret_cast<float4*>(&sT[r * LDT + c * 4]) = ts[r * 16 + c];
            }
        }
        __syncthreads();

        // K_t = T @ wk -> sA
#pragma unroll
        for (int i = 0; i < 4; i++)
#pragma unroll
            for (int j = 0; j < 8; j++) acc[i][j] = 0.0f;
        gemm_acc<CT>(sT, LDT, sW, ty4, tx8, acc);
#pragma unroll
        for (int i = 0; i < 4; i++) {
            *reinterpret_cast<float4*>(&sA[(ty4 + i) * LDA + tx8]) =
                make_float4(acc[i][0], acc[i][1], acc[i][2], acc[i][3]);
            *reinterpret_cast<float4*>(&sA[(ty4 + i) * LDA + tx8 + 4]) =
                make_float4(acc[i][4], acc[i][5], acc[i][6], acc[i][7]);
        }
        __syncthreads();

        // logits + online softmax update: one thread per (pixel, head)
        {
            int p = tid >> 2, h = tid & 3;
            const float* qp = &sQ[p * LDA + h * DH];
            const float* kp = &sA[p * LDA + h * DH];
            float l = 0.0f;
#pragma unroll
            for (int dd = 0; dd < DH; dd += 4) {
                float4 qv = *reinterpret_cast<const float4*>(&qp[dd]);
                float4 kv = *reinterpret_cast<const float4*>(&kp[dd]);
                l += qv.x * kv.x + qv.y * kv.y + qv.z * kv.z + qv.w * kv.w;
            }
            l += sBias[tt];
            float m_old = sM[tid];
            float m_new = fmaxf(m_old, l);
            float fac = __expf(m_old - m_new);
            float w   = __expf(l - m_new);
            sDen[tid] = sDen[tid] * fac + w;
            sM[tid]   = m_new;
            sFac[tid] = fac;
            sWt[tid]  = w;
        }
        __syncthreads();

        // V_t = T @ wv -> registers, fold into o_acc with rescale
#pragma unroll
        for (int i = 0; i < 4; i++)
#pragma unroll
            for (int j = 0; j < 8; j++) acc[i][j] = 0.0f;
        gemm_acc<CT>(sT, LDT, sW + 8192, ty4, tx8, acc);
        {
            int h = tx >> 2;   // all 8 cols of this thread share one head
#pragma unroll
            for (int i = 0; i < 4; i++) {
                float fac = sFac[(ty4 + i) * 4 + h];
                float w   = sWt[(ty4 + i) * 4 + h];
#pragma unroll
                for (int j = 0; j < 8; j++)
                    o_acc[i][j] = o_acc[i][j] * fac + w * acc[i][j];
            }
        }
    }
    __syncthreads();

    // ---- Phase 3: normalize, stage O in sA, load wo, epilogue GEMM ----
    {
        int h = tx >> 2;
#pragma unroll
        for (int i = 0; i < 4; i++) {
            float inv = 1.0f / sDen[(ty4 + i) * 4 + h];
            *reinterpret_cast<float4*>(&sA[(ty4 + i) * LDA + tx8]) =
                make_float4(o_acc[i][0]*inv, o_acc[i][1]*inv,
                            o_acc[i][2]*inv, o_acc[i][3]*inv);
            *reinterpret_cast<float4*>(&sA[(ty4 + i) * LDA + tx8 + 4]) =
                make_float4(o_acc[i][4]*inv, o_acc[i][5]*inv,
                            o_acc[i][6]*inv, o_acc[i][7]*inv);
        }
        const float4* wo4 = reinterpret_cast<const float4*>(wo);
        float4* sW4 = reinterpret_cast<float4*>(sW);
        for (int i = tid; i < 4096; i += 256) sW4[i] = wo4[i];
    }
    __syncthreads();

#pragma unroll
    for (int i = 0; i < 4; i++)
#pragma unroll
        for (int j = 0; j < 8; j++) acc[i][j] = 0.0f;
    gemm_acc<CZ>(sA, LDA, sW, ty4, tx8, acc);

#pragma unroll
    for (int i = 0; i < 4; i++) {
        size_t base = (size_t)(p0 + ty4 + i) * CZ + tx8;
        float4 r0 = make_float4(acc[i][0] + sBo[tx8 + 0], acc[i][1] + sBo[tx8 + 1],
                                acc[i][2] + sBo[tx8 + 2], acc[i][3] + sBo[tx8 + 3]);
        float4 r1 = make_float4(acc[i][4] + sBo[tx8 + 4], acc[i][5] + sBo[tx8 + 5],
                                acc[i][6] + sBo[tx8 + 6], acc[i][7] + sBo[tx8 + 7]);
        *reinterpret_cast<float4*>(&outp[base])     = r0;
        *reinterpret_cast<float4*>(&outp[base + 4]) = r1;
    }
}

extern "C" void kernel_launch(void* const* d_in, const int* in_sizes, int n_in,
                              void* d_out, int out_size)
{
    const float* t     = (const float*)d_in[0];
    const float* z     = (const float*)d_in[1];
    const float* tmask = (const float*)d_in[2];
    const float* wq    = (const float*)d_in[3];
    const float* wk    = (const float*)d_in[4];
    const float* wv    = (const float*)d_in[5];
    const float* wo    = (const float*)d_in[6];
    const float* bo    = (const float*)d_in[7];
    float* outp = (float*)d_out;

    const int smem_bytes = SMEM_FLOATS * (int)sizeof(float);
    cudaFuncSetAttribute(tpa_fused_kernel,
                         cudaFuncAttributeMaxDynamicSharedMemorySize, smem_bytes);

    dim3 grid(PIX / TILE_P);   // 4096 blocks
    dim3 block(256);
    tpa_fused_kernel<<<grid, block, smem_bytes>>>(
        t, z, tmask, wq, wk, wv, wo, bo, outp);
}

// round 6
// speedup vs baseline: 2.3073x; 2.3034x over previous
#include <cuda_runtime.h>
#include <cstdint>

// TemplatePointwiseAttention — fused fp32, algebraically restructured.
// logits via qk = q @ wk_h^T (per head), o via tbar = sum_t attn*tp, then @ wv_h.
// GEMM FLOPs: 51K FMA/pixel (vs 99K naive). qk + tbar + softmax state in registers.
// B=1, Nt=4, Nr=512, Ct=64, Cz=128, H=4, d=32.
// (Resubmission of R3 candidate — previous round hit a container infra failure.)

#define NR    512
#define NT    4
#define CT    64
#define CZ    128
#define PIX   (NR*NR)
#define TILE_P 64

#define LDA   132     // Z/Q/O row stride
#define LDT   68      // template tile row stride
#define LDQK  272     // tbar row stride = 4 heads * 68
#define HOFF  68      // per-head offset inside tbar row
#define LDKT  276     // wkT row stride (odd multiple-of-4 -> conflict-free column writes)

// smem (floats): regionA 64*272=17408 | sW 32*276=8832 (>= 8192 for other weights)
//                sT 64*68=4352 | sBias 4 | sBo 128
#define SW_FLOATS   8832
#define SMEM_FLOATS (17408 + SW_FLOATS + 4352 + 4 + 128)

// 4x8 register-tiled GEMM: C[64][128] += A[64][K] @ B[K][128], B stride = 128.
template<int K>
__device__ __forceinline__ void gemm_acc(const float* __restrict__ A, int lda,
                                         const float* __restrict__ B,
                                         int ty4, int tx8, float acc[4][8])
{
#pragma unroll 2
    for (int k4 = 0; k4 < K; k4 += 4) {
        float4 av[4];
#pragma unroll
        for (int i = 0; i < 4; i++)
            av[i] = *reinterpret_cast<const float4*>(&A[(ty4 + i) * lda + k4]);
#pragma unroll
        for (int kk = 0; kk < 4; kk++) {
            float4 b0 = *reinterpret_cast<const float4*>(&B[(k4 + kk) * CZ + tx8]);
            float4 b1 = *reinterpret_cast<const float4*>(&B[(k4 + kk) * CZ + tx8 + 4]);
#pragma unroll
            for (int i = 0; i < 4; i++) {
                float a = reinterpret_cast<const float*>(&av[i])[kk];
                acc[i][0] += a * b0.x; acc[i][1] += a * b0.y;
                acc[i][2] += a * b0.z; acc[i][3] += a * b0.w;
                acc[i][4] += a * b1.x; acc[i][5] += a * b1.y;
                acc[i][6] += a * b1.z; acc[i][7] += a * b1.w;
            }
        }
    }
}

__global__ __launch_bounds__(256)
void tpa_fused_kernel(const float* __restrict__ t,
                      const float* __restrict__ z,
                      const float* __restrict__ tmask,
                      const float* __restrict__ wq,
                      const float* __restrict__ wk,
                      const float* __restrict__ wv,
                      const float* __restrict__ wo,
                      const float* __restrict__ bo,
                      float* __restrict__ outp)
{
    extern __shared__ float smem[];
    float* regA  = smem;                    // 17408: Z | Q, later tbar, later O
    float* sW    = regA + 17408;            // 8832 weight staging
    float* sT    = sW + SW_FLOATS;          // 4352
    float* sBias = sT + 4352;               // 4
    float* sBo   = sBias + 4;               // 128

    float* sZ = regA;                       // [64][132]
    float* sQ = regA + 64 * LDA;            // [64][132]

    const int tid = threadIdx.x;
    // 4x8 GEMM indexing
    const int tx  = tid & 15;
    const int ty  = tid >> 4;
    const int tx8 = tx * 8;
    const int ty4 = ty * 4;
    // 8x8 / attention indexing
    const int lane = tid & 31;
    const int ty2  = tid >> 5;
    const int r0   = ty2 * 8;               // 8 rows
    const int h    = lane >> 3;             // head
    const int lh   = lane & 7;              // lane within head group
    const int cA   = lh * 4;                // c columns: cA..cA+3, cB..cB+3
    const int cB   = cA + 32;

    const int p0 = blockIdx.x * TILE_P;

    // ---- Phase 0: stage Z, wq chunk 0, bias, bo ----
    {
        const float4* z4 = reinterpret_cast<const float4*>(z);
#pragma unroll
        for (int k = 0; k < 8; k++) {
            int i = tid + k * 256;          // 2048 float4
            int r = i >> 5, c4 = i & 31;
            *reinterpret_cast<float4*>(&sZ[r * LDA + c4 * 4]) =
                z4[(size_t)(p0 + r) * 32 + c4];
        }
        const float4* wq4 = reinterpret_cast<const float4*>(wq);
        float4* sW4 = reinterpret_cast<float4*>(sW);
#pragma unroll
        for (int k = 0; k < 8; k++) sW4[tid + k * 256] = wq4[tid + k * 256];
        if (tid < NT) sBias[tid] = 100000.0f * (tmask[tid] - 1.0f);
        if (tid < 32)
            reinterpret_cast<float4*>(sBo)[tid] =
                reinterpret_cast<const float4*>(bo)[tid];
    }
    __syncthreads();

    // ---- Phase 1: Q = Z @ wq * (1/sqrt(32)), K split in two 64-chunks ----
    float acc[4][8];
#pragma unroll
    for (int i = 0; i < 4; i++)
#pragma unroll
        for (int j = 0; j < 8; j++) acc[i][j] = 0.0f;
    gemm_acc<64>(sZ, LDA, sW, ty4, tx8, acc);
    __syncthreads();
    {   // wq chunk 1
        const float4* wq4 = reinterpret_cast<const float4*>(wq + 64 * CZ);
        float4* sW4 = reinterpret_cast<float4*>(sW);
#pragma unroll
        for (int k = 0; k < 8; k++) sW4[tid + k * 256] = wq4[tid + k * 256];
    }
    __syncthreads();
    gemm_acc<64>(sZ + 64, LDA, sW, ty4, tx8, acc);
    {
        const float qs = 0.17677669529663687f;
#pragma unroll
        for (int i = 0; i < 4; i++) {
            *reinterpret_cast<float4*>(&sQ[(ty4 + i) * LDA + tx8]) =
                make_float4(acc[i][0]*qs, acc[i][1]*qs, acc[i][2]*qs, acc[i][3]*qs);
            *reinterpret_cast<float4*>(&sQ[(ty4 + i) * LDA + tx8 + 4]) =
                make_float4(acc[i][4]*qs, acc[i][5]*qs, acc[i][6]*qs, acc[i][7]*qs);
        }
    }
    __syncthreads();

    // ---- Phase 2: stage wk transposed: sW[dd*LDKT + h*HOFF + c] = wk[c][h*32+dd] ----
    {
        const float4* wk4 = reinterpret_cast<const float4*>(wk);
#pragma unroll
        for (int k = 0; k < 8; k++) {
            int i = tid + k * 256;          // 2048 float4 of wk [64][128]
            int c = i >> 5, j4 = i & 31;
            float4 v = wk4[i];
            int j0 = j4 * 4;
            int hh = j0 >> 5, dd = j0 & 31;
            float* dst = &sW[hh * HOFF + c];
            dst[(dd + 0) * LDKT] = v.x;
            dst[(dd + 1) * LDKT] = v.y;
            dst[(dd + 2) * LDKT] = v.z;
            dst[(dd + 3) * LDKT] = v.w;
        }
    }
    __syncthreads();

    // ---- Phase 3: qk_h[p] = q[p,h] @ wk_h^T  (8x8 per thread, in registers) ----
    float qk[8][8];
#pragma unroll
    for (int i = 0; i < 8; i++)
#pragma unroll
        for (int j = 0; j < 8; j++) qk[i][j] = 0.0f;
    {
        const float* Aq = sQ + h * 32;
        const float* Bk = sW + h * HOFF;
#pragma unroll
        for (int d4 = 0; d4 < 32; d4 += 4) {
            float4 av[8];
#pragma unroll
            for (int i = 0; i < 8; i++)
                av[i] = *reinterpret_cast<const float4*>(&Aq[(r0 + i) * LDA + d4]);
#pragma unroll
            for (int dd = 0; dd < 4; dd++) {
                float4 bA = *reinterpret_cast<const float4*>(&Bk[(d4 + dd) * LDKT + cA]);
                float4 bB = *reinterpret_cast<const float4*>(&Bk[(d4 + dd) * LDKT + cB]);
#pragma unroll
                for (int i = 0; i < 8; i++) {
                    float a = reinterpret_cast<const float*>(&av[i])[dd];
                    qk[i][0] += a * bA.x; qk[i][1] += a * bA.y;
                    qk[i][2] += a * bA.z; qk[i][3] += a * bA.w;
                    qk[i][4] += a * bB.x; qk[i][5] += a * bB.y;
                    qk[i][6] += a * bB.z; qk[i][7] += a * bB.w;
                }
            }
        }
    }
    __syncthreads();

    // ---- stage wv [64][128] (used after the template loop) ----
    {
        const float4* wv4 = reinterpret_cast<const float4*>(wv);
        float4* sW4 = reinterpret_cast<float4*>(sW);
#pragma unroll
        for (int k = 0; k < 8; k++) sW4[tid + k * 256] = wv4[tid + k * 256];
    }

    // ---- Phase 4: template loop, online softmax, tbar in registers ----
    float tb[8][8];
    float m8[8], den8[8];
#pragma unroll
    for (int i = 0; i < 8; i++) {
        m8[i] = -3.0e38f; den8[i] = 0.0f;
#pragma unroll
        for (int j = 0; j < 8; j++) tb[i][j] = 0.0f;
    }

    for (int tt = 0; tt < NT; tt++) {
        __syncthreads();
        {
            const float4* ts = reinterpret_cast<const float4*>(
                t + ((size_t)tt * PIX + p0) * CT);
#pragma unroll
            for (int k = 0; k < 4; k++) {
                int i = tid + k * 256;      // 1024 float4
                int r = i >> 4, c4 = i & 15;
                *reinterpret_cast<float4*>(&sT[r * LDT + c4 * 4]) = ts[r * 16 + c4];
            }
        }
        __syncthreads();

        float bias = sBias[tt];
#pragma unroll
        for (int i = 0; i < 8; i++) {
            int row = r0 + i;
            float4 tA = *reinterpret_cast<const float4*>(&sT[row * LDT + cA]);
            float4 tB = *reinterpret_cast<const float4*>(&sT[row * LDT + cB]);
            float part = qk[i][0]*tA.x + qk[i][1]*tA.y + qk[i][2]*tA.z + qk[i][3]*tA.w
                       + qk[i][4]*tB.x + qk[i][5]*tB.y + qk[i][6]*tB.z + qk[i][7]*tB.w;
            part += __shfl_xor_sync(0xffffffffu, part, 1);
            part += __shfl_xor_sync(0xffffffffu, part, 2);
            part += __shfl_xor_sync(0xffffffffu, part, 4);
            float l = part + bias;
            float mn  = fmaxf(m8[i], l);
            float fac = __expf(m8[i] - mn);
            float w   = __expf(l - mn);
            den8[i] = den8[i] * fac + w;
            m8[i]   = mn;
            tb[i][0] = tb[i][0]*fac + w*tA.x; tb[i][1] = tb[i][1]*fac + w*tA.y;
            tb[i][2] = tb[i][2]*fac + w*tA.z; tb[i][3] = tb[i][3]*fac + w*tA.w;
            tb[i][4] = tb[i][4]*fac + w*tB.x; tb[i][5] = tb[i][5]*fac + w*tB.y;
            tb[i][6] = tb[i][6]*fac + w*tB.z; tb[i][7] = tb[i][7]*fac + w*tB.w;
        }
    }

    // ---- Phase 5: normalize, store tbar to regA [p][h*68+c], stride 272 ----
#pragma unroll
    for (int i = 0; i < 8; i++) {
        float inv = 1.0f / den8[i];
        int row = r0 + i;
        *reinterpret_cast<float4*>(&regA[row * LDQK + h * HOFF + cA]) =
            make_float4(tb[i][0]*inv, tb[i][1]*inv, tb[i][2]*inv, tb[i][3]*inv);
        *reinterpret_cast<float4*>(&regA[row * LDQK + h * HOFF + cB]) =
            make_float4(tb[i][4]*inv, tb[i][5]*inv, tb[i][6]*inv, tb[i][7]*inv);
    }
    __syncthreads();

    // ---- Phase 6: o[p, h*32+dd] = tbar_h[p] @ wv_h  (4x8 tiling, K=64) ----
#pragma unroll
    for (int i = 0; i < 4; i++)
#pragma unroll
        for (int j = 0; j < 8; j++) acc[i][j] = 0.0f;
    gemm_acc<64>(regA + (tx >> 2) * HOFF, LDQK, sW, ty4, tx8, acc);
    __syncthreads();   // all tbar reads done before O overwrites regA

    // store O into regA [64][132]; stage wo chunk 0
#pragma unroll
    for (int i = 0; i < 4; i++) {
        *reinterpret_cast<float4*>(&regA[(ty4 + i) * LDA + tx8]) =
            make_float4(acc[i][0], acc[i][1], acc[i][2], acc[i][3]);
        *reinterpret_cast<float4*>(&regA[(ty4 + i) * LDA + tx8 + 4]) =
            make_float4(acc[i][4], acc[i][5], acc[i][6], acc[i][7]);
    }
    {
        const float4* wo4 = reinterpret_cast<const float4*>(wo);
        float4* sW4 = reinterpret_cast<float4*>(sW);
#pragma unroll
        for (int k = 0; k < 8; k++) sW4[tid + k * 256] = wo4[tid + k * 256];
    }
    __syncthreads();

    // ---- Phase 7: out = O @ wo + bo (K split in two 64-chunks) ----
#pragma unroll
    for (int i = 0; i < 4; i++)
#pragma unroll
        for (int j = 0; j < 8; j++) acc[i][j] = 0.0f;
    gemm_acc<64>(regA, LDA, sW, ty4, tx8, acc);
    __syncthreads();
    {
        const float4* wo4 = reinterpret_cast<const float4*>(wo + 64 * CZ);
        float4* sW4 = reinterpret_cast<float4*>(sW);
#pragma unroll
        for (int k = 0; k < 8; k++) sW4[tid + k * 256] = wo4[tid + k * 256];
    }
    __syncthreads();
    gemm_acc<64>(regA + 64, LDA, sW, ty4, tx8, acc);

#pragma unroll
    for (int i = 0; i < 4; i++) {
        size_t base = (size_t)(p0 + ty4 + i) * CZ + tx8;
        *reinterpret_cast<float4*>(&outp[base]) =
            make_float4(acc[i][0] + sBo[tx8+0], acc[i][1] + sBo[tx8+1],
                        acc[i][2] + sBo[tx8+2], acc[i][3] + sBo[tx8+3]);
        *reinterpret_cast<float4*>(&outp[base + 4]) =
            make_float4(acc[i][4] + sBo[tx8+4], acc[i][5] + sBo[tx8+5],
                        acc[i][6] + sBo[tx8+6], acc[i][7] + sBo[tx8+7]);
    }
}

extern "C" void kernel_launch(void* const* d_in, const int* in_sizes, int n_in,
                              void* d_out, int out_size)
{
    const float* t     = (const float*)d_in[0];
    const float* z     = (const float*)d_in[1];
    const float* tmask = (const float*)d_in[2];
    const float* wq    = (const float*)d_in[3];
    const float* wk    = (const float*)d_in[4];
    const float* wv    = (const float*)d_in[5];
    const float* wo    = (const float*)d_in[6];
    const float* bo    = (const float*)d_in[7];
    float* outp = (float*)d_out;

    const int smem_bytes = SMEM_FLOATS * (int)sizeof(float);
    cudaFuncSetAttribute(tpa_fused_kernel,
                         cudaFuncAttributeMaxDynamicSharedMemorySize, smem_bytes);

    tpa_fused_kernel<<<PIX / TILE_P, 256, smem_bytes>>>(
        t, z, tmask, wq, wk, wv, wo, bo, outp);
}

// round 10
// speedup vs baseline: 3.9355x; 1.7056x over previous
#include <cuda_runtime.h>
#include <cuda_fp16.h>
#include <cstdint>

// TemplatePointwiseAttention — folded-weights + mma.sync (HMMA) fp16 version.
//   wqk = s * wq_h @ wk_h^T   -> logits = Z @ wqk      (GEMM1: 128x256x128)
//   wvo = wv_h @ wo_h         -> out = tbar @ wvo + bo (GEMM2: 128x128x256)
// tcgen05 unavailable (harness PTX targets sm_103 base), so tensor work goes
// through mma.sync.m16n8k16 f16 with fp32 accumulators.

#define NT   4
#define CT   64
#define CZ   128
#define PIX  (512*512)
#define TP   128

#define QK_LD 272      // floats  (272 % 64 == 16 -> conflict-free f4 reads/stores)
#define Z_LD  136      // halfs   (≡ 8 mod 64 -> conflict-free mma fragment LDS)
#define WB_LD 136
#define TB_LD 264
#define VO_LD 264

#define QK_OFF   0                    // 128*272*4 = 139264
#define VO_OFF   0                    // wvo overlays QK after attention
#define Z_OFF    139264               // 128*136*2 = 34816
#define WB_OFF   (139264+34816)       // 34816
#define TB_OFF   139264               // tbar 128*264*2 = 67584 (over Z+WB)
#define MISC_OFF 208896               // bias 16B | bo 512B
#define SMEM_BYTES (208896 + 1024)

// precomputed folded weights, stored exactly in the smem tile image layout
__device__ __align__(16) __half g_wqk[2][128*136];   // [half][n*136 + k]
__device__ __align__(16) __half g_wvo[128*264];      // [j*264 + k]

__device__ __forceinline__ uint32_t packh2(float a, float b) {
    __half2 h = __floats2half2_rn(a, b);
    return *reinterpret_cast<uint32_t*>(&h);
}

__device__ __forceinline__ void mma16816(float* d, uint32_t a0, uint32_t a1,
                                         uint32_t a2, uint32_t a3,
                                         uint32_t b0, uint32_t b1) {
    asm volatile(
        "mma.sync.aligned.m16n8k16.row.col.f32.f16.f16.f32 "
        "{%0,%1,%2,%3}, {%4,%5,%6,%7}, {%8,%9}, {%0,%1,%2,%3};"
        : "+f"(d[0]), "+f"(d[1]), "+f"(d[2]), "+f"(d[3])
        : "r"(a0), "r"(a1), "r"(a2), "r"(a3), "r"(b0), "r"(b1));
}

// ---------------- setup kernels (run once per launch, trivial cost) ----------------
__global__ __launch_bounds__(256)
void setup_wqk(const float* __restrict__ wq, const float* __restrict__ wk) {
    int e = blockIdx.x * 256 + threadIdx.x;     // 32768 = 256 n * 128 k
    int n = e >> 7, k = e & 127;
    int h = n >> 6, c = n & 63;
    float v = 0.0f;
#pragma unroll
    for (int d = 0; d < 32; d++)
        v += wq[k * CZ + h * 32 + d] * wk[c * CZ + h * 32 + d];
    v *= 0.17677669529663687f;                  // 1/sqrt(32)
    g_wqk[n >> 7][(n & 127) * WB_LD + k] = __float2half(v);
}

__global__ __launch_bounds__(256)
void setup_wvo(const float* __restrict__ wv, const float* __restrict__ wo) {
    int e = blockIdx.x * 256 + threadIdx.x;     // 32768 = 128 j * 256 k
    int j = e >> 8, k = e & 255;
    int h = k >> 6, c = k & 63;
    float v = 0.0f;
#pragma unroll
    for (int d = 0; d < 32; d++)
        v += wv[c * CZ + h * 32 + d] * wo[(h * 32 + d) * CZ + j];
    g_wvo[j * VO_LD + k] = __float2half(v);
}

// ---------------- main kernel ----------------
__global__ __launch_bounds__(256, 1)
void tpa_mma_kernel(const float* __restrict__ t,
                    const float* __restrict__ z,
                    const float* __restrict__ tmask,
                    const float* __restrict__ bo,
                    float* __restrict__ outp)
{
    extern __shared__ uint8_t sm8[];
    float*  sQK   = (float*)(sm8 + QK_OFF);
    __half* sZ    = (__half*)(sm8 + Z_OFF);
    __half* sWb   = (__half*)(sm8 + WB_OFF);
    __half* sTB   = (__half*)(sm8 + TB_OFF);
    __half* sVO   = (__half*)(sm8 + VO_OFF);
    float*  sBias = (float*)(sm8 + MISC_OFF);
    float*  sBo   = (float*)(sm8 + MISC_OFF + 16);

    const int tid  = threadIdx.x;
    const int wid  = tid >> 5, lane = tid & 31;
    const int g    = lane >> 2, tg = lane & 3;    // mma fragment coords
    const int r0   = wid * 16;                    // warp row tile
    const int p0   = blockIdx.x * TP;

    // ---- stage Z (fp32 -> fp16) + wqk half0 + bias/bo ----
    {
        int row = tid >> 1, hf = tid & 1;
        const float4* zr = (const float4*)(z + (size_t)(p0 + row) * CZ + hf * 64);
        uint4* dst = (uint4*)(sZ + row * Z_LD + hf * 64);
#pragma unroll
        for (int i = 0; i < 8; i++) {
            float4 v0 = zr[2 * i], v1 = zr[2 * i + 1];
            dst[i] = make_uint4(packh2(v0.x, v0.y), packh2(v0.z, v0.w),
                                packh2(v1.x, v1.y), packh2(v1.z, v1.w));
        }
        const uint4* src = (const uint4*)g_wqk[0];
        uint4* d4 = (uint4*)sWb;
        for (int i = tid; i < 2176; i += 256) d4[i] = src[i];
        if (tid < NT) sBias[tid] = 100000.0f * (tmask[tid] - 1.0f);
        if (tid < 32) ((float4*)sBo)[tid] = ((const float4*)bo)[tid];
    }
    __syncthreads();

    // ---- GEMM1: QK[128][256] = Zh @ wqk^T, two 128-col halves ----
#pragma unroll
    for (int hf = 0; hf < 2; hf++) {
        if (hf == 1) {
            __syncthreads();
            const uint4* src = (const uint4*)g_wqk[1];
            uint4* d4 = (uint4*)sWb;
            for (int i = tid; i < 2176; i += 256) d4[i] = src[i];
            __syncthreads();
        }
        float d[16][4];
#pragma unroll
        for (int nt = 0; nt < 16; nt++)
            d[nt][0] = d[nt][1] = d[nt][2] = d[nt][3] = 0.0f;
#pragma unroll
        for (int kt = 0; kt < 8; kt++) {
            const __half* ab = sZ + (r0 + g) * Z_LD + kt * 16 + 2 * tg;
            uint32_t a0 = *(const uint32_t*)(ab);
            uint32_t a1 = *(const uint32_t*)(ab + 8 * Z_LD);
            uint32_t a2 = *(const uint32_t*)(ab + 8);
            uint32_t a3 = *(const uint32_t*)(ab + 8 * Z_LD + 8);
#pragma unroll
            for (int nt = 0; nt < 16; nt++) {
                const __half* bb = sWb + (nt * 8 + g) * WB_LD + kt * 16 + 2 * tg;
                uint32_t b0 = *(const uint32_t*)(bb);
                uint32_t b1 = *(const uint32_t*)(bb + 8);
                mma16816(d[nt], a0, a1, a2, a3, b0, b1);
            }
        }
#pragma unroll
        for (int nt = 0; nt < 16; nt++) {
            int col = hf * 128 + nt * 8 + 2 * tg;
            float* q0 = sQK + (r0 + g) * QK_LD + col;
            q0[0] = d[nt][0]; q0[1] = d[nt][1];
            float* q1 = q0 + 8 * QK_LD;
            q1[0] = d[nt][2]; q1[1] = d[nt][3];
        }
    }
    __syncthreads();

    // ---- attention: thread p = tid&127; slot handles heads {2s, 2s+1} ----
    {
        const int p = tid & 127, slot = tid >> 7;
#pragma unroll
        for (int r = 0; r < 2; r++) {
            const int h = slot * 2 + r;
            float qk[64];
            const float4* q4 = (const float4*)(sQK + p * QK_LD + h * 64);
#pragma unroll
            for (int i = 0; i < 16; i++) {
                float4 v = q4[i];
                qk[4*i] = v.x; qk[4*i+1] = v.y; qk[4*i+2] = v.z; qk[4*i+3] = v.w;
            }
            float lg[NT];
#pragma unroll
            for (int tt = 0; tt < NT; tt++) {
                const float4* tp4 =
                    (const float4*)(t + ((size_t)tt * PIX + p0 + p) * CT);
                float acc = 0.0f;
#pragma unroll
                for (int i = 0; i < 16; i++) {
                    float4 v = tp4[i];
                    acc += qk[4*i] * v.x + qk[4*i+1] * v.y
                         + qk[4*i+2] * v.z + qk[4*i+3] * v.w;
                }
                lg[tt] = acc + sBias[tt];
            }
            float m = fmaxf(fmaxf(lg[0], lg[1]), fmaxf(lg[2], lg[3]));
            float w[NT], den = 0.0f;
#pragma unroll
            for (int tt = 0; tt < NT; tt++) { w[tt] = __expf(lg[tt] - m); den += w[tt]; }
            float inv = 1.0f / den;

            float tb[64];
#pragma unroll
            for (int i = 0; i < 64; i++) tb[i] = 0.0f;
#pragma unroll
            for (int tt = 0; tt < NT; tt++) {
                float wt = w[tt] * inv;       // normalization folded in
                const float4* tp4 =
                    (const float4*)(t + ((size_t)tt * PIX + p0 + p) * CT);
#pragma unroll
                for (int i = 0; i < 16; i++) {  // L1 hit (loaded in pass 1)
                    float4 v = tp4[i];
                    tb[4*i]   += wt * v.x; tb[4*i+1] += wt * v.y;
                    tb[4*i+2] += wt * v.z; tb[4*i+3] += wt * v.w;
                }
            }
            uint4* dst = (uint4*)(sTB + p * TB_LD + h * 64);
#pragma unroll
            for (int c4 = 0; c4 < 8; c4++) {
                dst[c4] = make_uint4(packh2(tb[8*c4+0], tb[8*c4+1]),
                                     packh2(tb[8*c4+2], tb[8*c4+3]),
                                     packh2(tb[8*c4+4], tb[8*c4+5]),
                                     packh2(tb[8*c4+6], tb[8*c4+7]));
            }
        }
    }
    __syncthreads();

    // ---- load wvo (overlays dead QK region) ----
    {
        const uint4* src = (const uint4*)g_wvo;
        uint4* d4 = (uint4*)sVO;
        for (int i = tid; i < 4224; i += 256) d4[i] = src[i];
    }
    __syncthreads();

    // ---- GEMM2: out[128][128] = tbar @ wvo^T ----
    float e[16][4];
#pragma unroll
    for (int nt = 0; nt < 16; nt++)
        e[nt][0] = e[nt][1] = e[nt][2] = e[nt][3] = 0.0f;
#pragma unroll
    for (int kt = 0; kt < 16; kt++) {
        const __half* ab = sTB + (r0 + g) * TB_LD + kt * 16 + 2 * tg;
        uint32_t a0 = *(const uint32_t*)(ab);
        uint32_t a1 = *(const uint32_t*)(ab + 8 * TB_LD);
        uint32_t a2 = *(const uint32_t*)(ab + 8);
        uint32_t a3 = *(const uint32_t*)(ab + 8 * TB_LD + 8);
#pragma unroll
        for (int nt = 0; nt < 16; nt++) {
            const __half* bb = sVO + (nt * 8 + g) * VO_LD + kt * 16 + 2 * tg;
            uint32_t b0 = *(const uint32_t*)(bb);
            uint32_t b1 = *(const uint32_t*)(bb + 8);
            mma16816(e[nt], a0, a1, a2, a3, b0, b1);
        }
    }

    // ---- epilogue: add bo, store ----
    {
        float* o0 = outp + (size_t)(p0 + r0 + g) * CZ;
        float* o1 = o0 + 8 * CZ;
#pragma unroll
        for (int nt = 0; nt < 16; nt++) {
            int c0 = nt * 8 + 2 * tg;
            float b0f = sBo[c0], b1f = sBo[c0 + 1];
            *(float2*)(o0 + c0) = make_float2(e[nt][0] + b0f, e[nt][1] + b1f);
            *(float2*)(o1 + c0) = make_float2(e[nt][2] + b0f, e[nt][3] + b1f);
        }
    }
}

extern "C" void kernel_launch(void* const* d_in, const int* in_sizes, int n_in,
                              void* d_out, int out_size)
{
    const float* t     = (const float*)d_in[0];
    const float* z     = (const float*)d_in[1];
    const float* tmask = (const float*)d_in[2];
    const float* wq    = (const float*)d_in[3];
    const float* wk    = (const float*)d_in[4];
    const float* wv    = (const float*)d_in[5];
    const float* wo    = (const float*)d_in[6];
    const float* bo    = (const float*)d_in[7];
    float* outp = (float*)d_out;

    setup_wqk<<<128, 256>>>(wq, wk);
    setup_wvo<<<128, 256>>>(wv, wo);

    cudaFuncSetAttribute(tpa_mma_kernel,
                         cudaFuncAttributeMaxDynamicSharedMemorySize, SMEM_BYTES);
    tpa_mma_kernel<<<PIX / TP, 256, SMEM_BYTES>>>(t, z, tmask, bo, outp);
}

// round 12
// speedup vs baseline: 4.9040x; 1.2461x over previous
#include <cuda_runtime.h>
#include <cuda_fp16.h>
#include <cstdint>

// TemplatePointwiseAttention — folded weights + mma.sync (HMMA) fp16, v2.
//   wqk = s * wq_h @ wk_h^T   -> logits = Z @ wqk      (GEMM1: 128x256x128)
//   wvo = wv_h @ wo_h         -> out = tbar @ wvo + bo (GEMM2: 128x128x256)
// v2: t-tile staged once to smem (fp16), tbar embedded into dead QK rows
// (xor-swizzled), ldmatrix.x4 fragment loads.
// (Resubmission — previous round hit a container infra failure, kernel never ran.)

#define NT   4
#define CT   64
#define CZ   128
#define PIX  (512*512)
#define TP   128

#define QK_LD 272       // floats; row = 1088 B
#define Z_LD  136       // halfs  (272 B row)
#define WB_LD 136
#define TT_LD 264       // halfs  (528 B row): t-tile [p][tt*64+c]
#define VO_LD 264

#define QK_OFF   0                       // 128*1088 = 139264
#define Z_OFF    139264                  // 34816
#define WB_OFF   (139264+34816)          // 34816  (ends 208896)
#define TT_OFF   139264                  // 128*528 = 67584 (overlays Z+WB)
#define VO_OFF   139264                  // 67584 (overlays TT)
#define MISC_OFF 208896                  // bias 16B | bo 512B
#define SMEM_BYTES (208896 + 1024)

__device__ __align__(16) __half g_wqk[2][128*136];   // [half][n*136 + k]
__device__ __align__(16) __half g_wvo[128*264];      // [j*264 + k]

__device__ __forceinline__ uint32_t packh2(float a, float b) {
    __half2 h = __floats2half2_rn(a, b);
    return *reinterpret_cast<uint32_t*>(&h);
}
__device__ __forceinline__ float2 h2f(uint32_t u) {
    return __half22float2(*reinterpret_cast<__half2*>(&u));
}
__device__ __forceinline__ uint32_t smem_u32(const void* p) {
    uint32_t a;
    asm("{ .reg .u64 t; cvta.to.shared.u64 t, %1; cvt.u32.u64 %0, t; }"
        : "=r"(a) : "l"(p));
    return a;
}
__device__ __forceinline__ void ldm_x4(uint32_t& r0, uint32_t& r1,
                                       uint32_t& r2, uint32_t& r3, uint32_t a) {
    asm volatile("ldmatrix.sync.aligned.m8n8.x4.shared.b16 {%0,%1,%2,%3}, [%4];"
                 : "=r"(r0), "=r"(r1), "=r"(r2), "=r"(r3) : "r"(a));
}
__device__ __forceinline__ void mma16816(float* d, uint32_t a0, uint32_t a1,
                                         uint32_t a2, uint32_t a3,
                                         uint32_t b0, uint32_t b1) {
    asm volatile(
        "mma.sync.aligned.m16n8k16.row.col.f32.f16.f16.f32 "
        "{%0,%1,%2,%3}, {%4,%5,%6,%7}, {%8,%9}, {%0,%1,%2,%3};"
        : "+f"(d[0]), "+f"(d[1]), "+f"(d[2]), "+f"(d[3])
        : "r"(a0), "r"(a1), "r"(a2), "r"(a3), "r"(b0), "r"(b1));
}

// ---------------- setup kernels ----------------
__global__ __launch_bounds__(256)
void setup_wqk(const float* __restrict__ wq, const float* __restrict__ wk) {
    int e = blockIdx.x * 256 + threadIdx.x;     // 32768 = 256 n * 128 k
    int n = e >> 7, k = e & 127;
    int h = n >> 6, c = n & 63;
    float v = 0.0f;
#pragma unroll
    for (int d = 0; d < 32; d++)
        v += wq[k * CZ + h * 32 + d] * wk[c * CZ + h * 32 + d];
    v *= 0.17677669529663687f;                  // 1/sqrt(32)
    g_wqk[n >> 7][(n & 127) * WB_LD + k] = __float2half(v);
}
__global__ __launch_bounds__(256)
void setup_wvo(const float* __restrict__ wv, const float* __restrict__ wo) {
    int e = blockIdx.x * 256 + threadIdx.x;     // 32768 = 128 j * 256 k
    int j = e >> 8, k = e & 255;
    int h = k >> 6, c = k & 63;
    float v = 0.0f;
#pragma unroll
    for (int d = 0; d < 32; d++)
        v += wv[c * CZ + h * 32 + d] * wo[(h * 32 + d) * CZ + j];
    g_wvo[j * VO_LD + k] = __float2half(v);
}

// ---------------- main kernel ----------------
__global__ __launch_bounds__(256, 1)
void tpa_mma_kernel(const float* __restrict__ t,
                    const float* __restrict__ z,
                    const float* __restrict__ tmask,
                    const float* __restrict__ bo,
                    float* __restrict__ outp)
{
    extern __shared__ uint8_t sm8[];
    float*  sQK   = (float*)(sm8 + QK_OFF);
    __half* sZ    = (__half*)(sm8 + Z_OFF);
    float*  sBias = (float*)(sm8 + MISC_OFF);
    float*  sBo   = (float*)(sm8 + MISC_OFF + 16);
    const uint32_t sbase = smem_u32(sm8);

    const int tid  = threadIdx.x;
    const int wid  = tid >> 5, lane = tid & 31;
    const int g    = lane >> 2, tg = lane & 3;
    const int quad = lane >> 3, lr = lane & 7;
    const int r0   = wid * 16;
    const int p0   = blockIdx.x * TP;

    // ldmatrix lane address bases
    const uint32_t aAddr1 = sbase + Z_OFF +
        (uint32_t)(r0 + lr + (quad & 1) * 8) * (Z_LD * 2) + (quad >> 1) * 16;
    const uint32_t bAddr1 = sbase + WB_OFF +
        (uint32_t)(lr + (quad >> 1) * 8) * (WB_LD * 2) + (quad & 1) * 16;
    const uint32_t bAddr2 = sbase + VO_OFF +
        (uint32_t)(lr + (quad >> 1) * 8) * (VO_LD * 2) + (quad & 1) * 16;

    // ---- Phase 0: stage Z (fp32->fp16) + wqk half0 + bias/bo ----
    {
        int row = tid >> 1, hf = tid & 1;
        const float4* zr = (const float4*)(z + (size_t)(p0 + row) * CZ + hf * 64);
        uint4* dst = (uint4*)(sZ + row * Z_LD + hf * 64);
#pragma unroll
        for (int i = 0; i < 8; i++) {
            float4 v0 = zr[2 * i], v1 = zr[2 * i + 1];
            dst[i] = make_uint4(packh2(v0.x, v0.y), packh2(v0.z, v0.w),
                                packh2(v1.x, v1.y), packh2(v1.z, v1.w));
        }
        const uint4* src = (const uint4*)g_wqk[0];
        uint4* d4 = (uint4*)(sm8 + WB_OFF);
        for (int i = tid; i < 2176; i += 256) d4[i] = src[i];
        if (tid < NT) sBias[tid] = 100000.0f * (tmask[tid] - 1.0f);
        if (tid < 32) ((float4*)sBo)[tid] = ((const float4*)bo)[tid];
    }
    __syncthreads();

    // ---- GEMM1: QK[128][256] = Zh @ wqk^T (two 128-col halves) ----
#pragma unroll
    for (int hf = 0; hf < 2; hf++) {
        if (hf == 1) {
            __syncthreads();
            const uint4* src = (const uint4*)g_wqk[1];
            uint4* d4 = (uint4*)(sm8 + WB_OFF);
            for (int i = tid; i < 2176; i += 256) d4[i] = src[i];
            __syncthreads();
        }
        float d[16][4];
#pragma unroll
        for (int nt = 0; nt < 16; nt++)
            d[nt][0] = d[nt][1] = d[nt][2] = d[nt][3] = 0.0f;
#pragma unroll
        for (int kt = 0; kt < 8; kt++) {
            uint32_t a0, a1, a2, a3;
            ldm_x4(a0, a1, a2, a3, aAddr1 + kt * 32);
#pragma unroll
            for (int np = 0; np < 8; np++) {
                uint32_t b0, b1, b2, b3;
                ldm_x4(b0, b1, b2, b3, bAddr1 + np * (16 * WB_LD * 2) + kt * 32);
                mma16816(d[2 * np],     a0, a1, a2, a3, b0, b1);
                mma16816(d[2 * np + 1], a0, a1, a2, a3, b2, b3);
            }
        }
#pragma unroll
        for (int nt = 0; nt < 16; nt++) {
            int col = hf * 128 + nt * 8 + 2 * tg;
            float* q0 = sQK + (r0 + g) * QK_LD + col;
            q0[0] = d[nt][0]; q0[1] = d[nt][1];
            float* q1 = q0 + 8 * QK_LD;
            q1[0] = d[nt][2]; q1[1] = d[nt][3];
        }
    }
    __syncthreads();

    // ---- stage t-tile to smem fp16: sTT[p][tt*64+c], stride 264 halfs ----
#pragma unroll
    for (int s = 0; s < 2; s++) {
        int rowid = tid + s * 256;               // 0..511 = (tt, p)
        int tt = rowid >> 7, p = rowid & 127;
        const float4* src = (const float4*)(t + ((size_t)tt * PIX + p0 + p) * CT);
        uint4* dst = (uint4*)(sm8 + TT_OFF + (uint32_t)p * (TT_LD * 2) + tt * 128);
#pragma unroll
        for (int i = 0; i < 8; i++) {
            float4 v0 = src[2 * i], v1 = src[2 * i + 1];
            dst[i] = make_uint4(packh2(v0.x, v0.y), packh2(v0.z, v0.w),
                                packh2(v1.x, v1.y), packh2(v1.z, v1.w));
        }
    }
    __syncthreads();

    // ---- attention: thread p = tid&127; slot handles heads {2s, 2s+1} ----
    {
        const int p = tid & 127, slot = tid >> 7;
        const uint8_t* trow = sm8 + TT_OFF + (uint32_t)p * (TT_LD * 2);
        uint8_t* qrow = sm8 + QK_OFF + (uint32_t)p * (QK_LD * 4);
        const int key = p & 7;
#pragma unroll
        for (int r = 0; r < 2; r++) {
            const int h = slot * 2 + r;
            float qk[64];
            const float4* q4 = (const float4*)(sQK + p * QK_LD + h * 64);
#pragma unroll
            for (int i = 0; i < 16; i++) {
                float4 v = q4[i];
                qk[4*i] = v.x; qk[4*i+1] = v.y; qk[4*i+2] = v.z; qk[4*i+3] = v.w;
            }
            float lg[NT];
#pragma unroll
            for (int tt = 0; tt < NT; tt++) {
                const uint4* tr = (const uint4*)(trow + tt * 128);
                float acc = 0.0f;
#pragma unroll
                for (int j = 0; j < 8; j++) {
                    uint4 u = tr[j];
                    float2 f0 = h2f(u.x), f1 = h2f(u.y), f2 = h2f(u.z), f3 = h2f(u.w);
                    acc += qk[8*j]   * f0.x + qk[8*j+1] * f0.y
                         + qk[8*j+2] * f1.x + qk[8*j+3] * f1.y
                         + qk[8*j+4] * f2.x + qk[8*j+5] * f2.y
                         + qk[8*j+6] * f3.x + qk[8*j+7] * f3.y;
                }
                lg[tt] = acc + sBias[tt];
            }
            float m = fmaxf(fmaxf(lg[0], lg[1]), fmaxf(lg[2], lg[3]));
            float w[NT], den = 0.0f;
#pragma unroll
            for (int tt = 0; tt < NT; tt++) { w[tt] = __expf(lg[tt] - m); den += w[tt]; }
            float inv = 1.0f / den;
#pragma unroll
            for (int tt = 0; tt < NT; tt++) w[tt] *= inv;

            // pass2: tbar block-by-block, store fp16 into own dead QK cols
            const uint4* t0 = (const uint4*)(trow);
            const uint4* t1 = (const uint4*)(trow + 128);
            const uint4* t2 = (const uint4*)(trow + 256);
            const uint4* t3 = (const uint4*)(trow + 384);
#pragma unroll
            for (int j = 0; j < 8; j++) {
                uint4 ua = t0[j], ub = t1[j], uc = t2[j], ud = t3[j];
                uint32_t outw[4];
#pragma unroll
                for (int q = 0; q < 4; q++) {
                    uint32_t xa = (&ua.x)[q], xb = (&ub.x)[q],
                             xc = (&uc.x)[q], xd = (&ud.x)[q];
                    float2 fa = h2f(xa), fb = h2f(xb), fc = h2f(xc), fd = h2f(xd);
                    float ox = w[0]*fa.x + w[1]*fb.x + w[2]*fc.x + w[3]*fd.x;
                    float oy = w[0]*fa.y + w[1]*fb.y + w[2]*fc.y + w[3]*fd.y;
                    outw[q] = packh2(ox, oy);
                }
                int blk = h * 16 + j;
                *(uint4*)(qrow + (uint32_t)((blk ^ key) << 4)) =
                    make_uint4(outw[0], outw[1], outw[2], outw[3]);
            }
        }
    }
    __syncthreads();

    // ---- load wvo (overlays dead t-tile) ----
    {
        const uint4* src = (const uint4*)g_wvo;
        uint4* d4 = (uint4*)(sm8 + VO_OFF);
        for (int i = tid; i < 4224; i += 256) d4[i] = src[i];
    }
    __syncthreads();

    // ---- GEMM2: out[128][128] = tbar @ wvo^T (A from embedded QK rows) ----
    float e[16][4];
#pragma unroll
    for (int nt = 0; nt < 16; nt++)
        e[nt][0] = e[nt][1] = e[nt][2] = e[nt][3] = 0.0f;
    {
        const uint8_t* baseA = sm8 + QK_OFF + (uint32_t)(r0 + g) * (QK_LD * 4) + tg * 4;
#pragma unroll
        for (int kt = 0; kt < 16; kt++) {
            int h = kt >> 2;
            int blk0 = h * 16 + (kt & 3) * 2;
            uint32_t o0 = (uint32_t)((blk0 ^ g) << 4);
            uint32_t o1 = (uint32_t)(((blk0 + 1) ^ g) << 4);
            uint32_t a0 = *(const uint32_t*)(baseA + o0);
            uint32_t a2 = *(const uint32_t*)(baseA + o1);
            uint32_t a1 = *(const uint32_t*)(baseA + 8 * (QK_LD * 4) + o0);
            uint32_t a3 = *(const uint32_t*)(baseA + 8 * (QK_LD * 4) + o1);
#pragma unroll
            for (int np = 0; np < 8; np++) {
                uint32_t b0, b1, b2, b3;
                ldm_x4(b0, b1, b2, b3, bAddr2 + np * (16 * VO_LD * 2) + kt * 32);
                mma16816(e[2 * np],     a0, a1, a2, a3, b0, b1);
                mma16816(e[2 * np + 1], a0, a1, a2, a3, b2, b3);
            }
        }
    }

    // ---- epilogue: add bo, store ----
    {
        float* o0 = outp + (size_t)(p0 + r0 + g) * CZ;
        float* o1 = o0 + 8 * CZ;
#pragma unroll
        for (int nt = 0; nt < 16; nt++) {
            int c0 = nt * 8 + 2 * tg;
            float b0f = sBo[c0], b1f = sBo[c0 + 1];
            *(float2*)(o0 + c0) = make_float2(e[nt][0] + b0f, e[nt][1] + b1f);
            *(float2*)(o1 + c0) = make_float2(e[nt][2] + b0f, e[nt][3] + b1f);
        }
    }
}

extern "C" void kernel_launch(void* const* d_in, const int* in_sizes, int n_in,
                              void* d_out, int out_size)
{
    const float* t     = (const float*)d_in[0];
    const float* z     = (const float*)d_in[1];
    const float* tmask = (const float*)d_in[2];
    const float* wq    = (const float*)d_in[3];
    const float* wk    = (const float*)d_in[4];
    const float* wv    = (const float*)d_in[5];
    const float* wo    = (const float*)d_in[6];
    const float* bo    = (const float*)d_in[7];
    float* outp = (float*)d_out;

    setup_wqk<<<128, 256>>>(wq, wk);
    setup_wvo<<<128, 256>>>(wv, wo);

    cudaFuncSetAttribute(tpa_mma_kernel,
                         cudaFuncAttributeMaxDynamicSharedMemorySize, SMEM_BYTES);
    tpa_mma_kernel<<<PIX / TP, 256, SMEM_BYTES>>>(t, z, tmask, bo, outp);
}

// round 16
// speedup vs baseline: 8.8664x; 1.8080x over previous
#include <cuda_runtime.h>
#include <cuda_fp16.h>
#include <cstdint>

// TemplatePointwiseAttention — folded weights + mma.sync fp16, v3.
//   wqk = s * wq_h @ wk_h^T   -> logits = Z @ wqk      (GEMM1: 128x256x128)
//   wvo = wv_h @ wo_h         -> out = tbar @ wvo + bo (GEMM2: 128x128x256)
// v3: QK and tbar live ENTIRELY in registers (quad-shfl logits; tbar regs are
// the GEMM2 A-fragments). t prefetched fp32 via cp.async; wvo prefetched
// during attention. smem: Z | wqk-half (wvo overlays) | t fp32.

#define NT   4
#define CT   64
#define CZ   128
#define PIX  (512*512)
#define TP   128

#define Z_LD  136       // halfs (272 B row)
#define WB_LD 136
#define VO_LD 264
#define T_LD  264       // floats (1056 B row)

#define Z_OFF    0                    // 34816
#define WB_OFF   34816                // 34816 (ends 69632)
#define VO_OFF   0                    // wvo 67584 overlays Z+WB after GEMM1
#define T_OFF    69632                // 128*1056 = 135168 (ends 204800)
#define MISC_OFF 204800               // bias 16B | bo 512B
#define SMEM_BYTES (204800 + 1024)

__device__ __align__(16) __half g_wqk[2][128*136];   // [half][n*136 + k]
__device__ __align__(16) __half g_wvo[128*264];      // [j*264 + k]

__device__ __forceinline__ uint32_t packh2(float a, float b) {
    __half2 h = __floats2half2_rn(a, b);
    return *reinterpret_cast<uint32_t*>(&h);
}
__device__ __forceinline__ uint32_t smem_u32(const void* p) {
    uint32_t a;
    asm("{ .reg .u64 t; cvta.to.shared.u64 t, %1; cvt.u32.u64 %0, t; }"
        : "=r"(a) : "l"(p));
    return a;
}
__device__ __forceinline__ void ldm_x4(uint32_t& r0, uint32_t& r1,
                                       uint32_t& r2, uint32_t& r3, uint32_t a) {
    asm volatile("ldmatrix.sync.aligned.m8n8.x4.shared.b16 {%0,%1,%2,%3}, [%4];"
                 : "=r"(r0), "=r"(r1), "=r"(r2), "=r"(r3) : "r"(a));
}
__device__ __forceinline__ void mma16816(float* d, uint32_t a0, uint32_t a1,
                                         uint32_t a2, uint32_t a3,
                                         uint32_t b0, uint32_t b1) {
    asm volatile(
        "mma.sync.aligned.m16n8k16.row.col.f32.f16.f16.f32 "
        "{%0,%1,%2,%3}, {%4,%5,%6,%7}, {%8,%9}, {%0,%1,%2,%3};"
        : "+f"(d[0]), "+f"(d[1]), "+f"(d[2]), "+f"(d[3])
        : "r"(a0), "r"(a1), "r"(a2), "r"(a3), "r"(b0), "r"(b1));
}
#define CP16(dst, src) \
    asm volatile("cp.async.cg.shared.global [%0], [%1], 16;" \
                 :: "r"(dst), "l"(src) : "memory")
#define CP_COMMIT() asm volatile("cp.async.commit_group;" ::: "memory")
#define CP_WAIT(n)  asm volatile("cp.async.wait_group %0;" :: "n"(n) : "memory")

// ---------------- setup kernels ----------------
__global__ __launch_bounds__(256)
void setup_wqk(const float* __restrict__ wq, const float* __restrict__ wk) {
    int e = blockIdx.x * 256 + threadIdx.x;     // 32768 = 256 n * 128 k
    int n = e >> 7, k = e & 127;
    int h = n >> 6, c = n & 63;
    float v = 0.0f;
#pragma unroll
    for (int d = 0; d < 32; d++)
        v += wq[k * CZ + h * 32 + d] * wk[c * CZ + h * 32 + d];
    v *= 0.17677669529663687f;                  // 1/sqrt(32)
    g_wqk[n >> 7][(n & 127) * WB_LD + k] = __float2half(v);
}
__global__ __launch_bounds__(256)
void setup_wvo(const float* __restrict__ wv, const float* __restrict__ wo) {
    int e = blockIdx.x * 256 + threadIdx.x;     // 32768 = 128 j * 256 k
    int j = e >> 8, k = e & 255;
    int h = k >> 6, c = k & 63;
    float v = 0.0f;
#pragma unroll
    for (int d = 0; d < 32; d++)
        v += wv[c * CZ + h * 32 + d] * wo[(h * 32 + d) * CZ + j];
    g_wvo[j * VO_LD + k] = __float2half(v);
}

// ---------------- main kernel ----------------
__global__ __launch_bounds__(256, 1)
void tpa_mma_kernel(const float* __restrict__ t,
                    const float* __restrict__ z,
                    const float* __restrict__ tmask,
                    const float* __restrict__ bo,
                    float* __restrict__ outp)
{
    extern __shared__ uint8_t sm8[];
    __half* sZ    = (__half*)(sm8 + Z_OFF);
    float*  sT    = (float*)(sm8 + T_OFF);
    float*  sBias = (float*)(sm8 + MISC_OFF);
    float*  sBo   = (float*)(sm8 + MISC_OFF + 16);
    const uint32_t sbase = smem_u32(sm8);

    const int tid  = threadIdx.x;
    const int wid  = tid >> 5, lane = tid & 31;
    const int g    = lane >> 2, tg = lane & 3;
    const int quad = lane >> 3, lr = lane & 7;
    const int r0   = wid * 16;
    const int p0   = blockIdx.x * TP;

    const uint32_t aAddr1 = sbase + Z_OFF +
        (uint32_t)(r0 + lr + (quad & 1) * 8) * (Z_LD * 2) + (quad >> 1) * 16;
    const uint32_t bAddr1 = sbase + WB_OFF +
        (uint32_t)(lr + (quad >> 1) * 8) * (WB_LD * 2) + (quad & 1) * 16;
    const uint32_t bAddr2 = sbase + VO_OFF +
        (uint32_t)(lr + (quad >> 1) * 8) * (VO_LD * 2) + (quad & 1) * 16;

    // ---- prefetch group A: wqk half0 (fp16, linear) ----
    {
        const uint8_t* src = (const uint8_t*)g_wqk[0];
#pragma unroll
        for (int i = 0; i < 9; i++) {
            int c = tid + i * 256;                 // 2176 chunks
            if (c < 2176) CP16(sbase + WB_OFF + c * 16, src + c * 16);
        }
    }
    CP_COMMIT();
    // ---- prefetch group B: t tile fp32 -> sT[p][tt*64+c], stride 264 ----
    {
#pragma unroll
        for (int i = 0; i < 32; i++) {
            int idx = tid + i * 256;               // 8192 chunks of 16B
            int row = idx >> 4, ch = idx & 15;     // row = tt*128 + p
            int tt = row >> 7, p = row & 127;
            const uint8_t* src = (const uint8_t*)(t +
                ((size_t)tt * PIX + p0 + p) * CT) + ch * 16;
            CP16(sbase + T_OFF + (uint32_t)p * (T_LD * 4) + tt * 256 + ch * 16, src);
        }
    }
    CP_COMMIT();

    // ---- stage Z (fp32->fp16, plain loads overlap cp.async) + bias/bo ----
    {
        int row = tid >> 1, hf = tid & 1;
        const float4* zr = (const float4*)(z + (size_t)(p0 + row) * CZ + hf * 64);
        uint4* dst = (uint4*)(sZ + row * Z_LD + hf * 64);
#pragma unroll
        for (int i = 0; i < 8; i++) {
            float4 v0 = zr[2 * i], v1 = zr[2 * i + 1];
            dst[i] = make_uint4(packh2(v0.x, v0.y), packh2(v0.z, v0.w),
                                packh2(v1.x, v1.y), packh2(v1.z, v1.w));
        }
        if (tid < NT) sBias[tid] = 100000.0f * (tmask[tid] - 1.0f);
        if (tid < 32) ((float4*)sBo)[tid] = ((const float4*)bo)[tid];
    }
    CP_WAIT(1);                 // wqk0 landed (groups retire in order)
    __syncthreads();

    // ---- GEMM1 half0 -> dA (heads 0,1) ----
    float dA[16][4], dB[16][4];
#pragma unroll
    for (int nt = 0; nt < 16; nt++)
        dA[nt][0] = dA[nt][1] = dA[nt][2] = dA[nt][3] = 0.0f;
#pragma unroll
    for (int kt = 0; kt < 8; kt++) {
        uint32_t a0, a1, a2, a3;
        ldm_x4(a0, a1, a2, a3, aAddr1 + kt * 32);
#pragma unroll
        for (int np = 0; np < 8; np++) {
            uint32_t b0, b1, b2, b3;
            ldm_x4(b0, b1, b2, b3, bAddr1 + np * (16 * WB_LD * 2) + kt * 32);
            mma16816(dA[2 * np],     a0, a1, a2, a3, b0, b1);
            mma16816(dA[2 * np + 1], a0, a1, a2, a3, b2, b3);
        }
    }
    __syncthreads();            // WB half0 consumed

    // ---- load wqk half1 (plain; t cp.async still streaming) ----
    {
        const uint4* src = (const uint4*)g_wqk[1];
        uint4* d4 = (uint4*)(sm8 + WB_OFF);
#pragma unroll
        for (int i = 0; i < 9; i++) {
            int c = tid + i * 256;
            if (c < 2176) d4[c] = src[c];
        }
    }
    __syncthreads();

    // ---- GEMM1 half1 -> dB (heads 2,3) ----
#pragma unroll
    for (int nt = 0; nt < 16; nt++)
        dB[nt][0] = dB[nt][1] = dB[nt][2] = dB[nt][3] = 0.0f;
#pragma unroll
    for (int kt = 0; kt < 8; kt++) {
        uint32_t a0, a1, a2, a3;
        ldm_x4(a0, a1, a2, a3, aAddr1 + kt * 32);
#pragma unroll
        for (int np = 0; np < 8; np++) {
            uint32_t b0, b1, b2, b3;
            ldm_x4(b0, b1, b2, b3, bAddr1 + np * (16 * WB_LD * 2) + kt * 32);
            mma16816(dB[2 * np],     a0, a1, a2, a3, b0, b1);
            mma16816(dB[2 * np + 1], a0, a1, a2, a3, b2, b3);
        }
    }
    CP_WAIT(0);                 // t tile landed
    __syncthreads();            // Z + WB now dead everywhere

    // ---- prefetch wvo into VO region (overlays Z+WB), runs under attention ----
    {
        const uint8_t* src = (const uint8_t*)g_wvo;
#pragma unroll
        for (int i = 0; i < 17; i++) {
            int c = tid + i * 256;                 // 4224 chunks
            if (c < 4224) CP16(sbase + VO_OFF + c * 16, src + c * 16);
        }
    }
    CP_COMMIT();

    // ---- attention fully in registers ----
    // quad (lanes 4g..4g+3) covers all 256 QK cols of rows r0+g, r0+g+8.
    // lane's cols per head: c = 8b + 2tg + {0,1}, b = 0..7.
    uint32_t tbar[2][4][8];     // [rr][h][b] packed fp16 pairs = GEMM2 A frags
#pragma unroll
    for (int rr = 0; rr < 2; rr++) {
        const float* trow = sT + (uint32_t)(r0 + g + rr * 8) * T_LD;
        float lg[4][NT];
#pragma unroll
        for (int tt = 0; tt < NT; tt++) {
            float2 tv[8];
#pragma unroll
            for (int b = 0; b < 8; b++)
                tv[b] = *(const float2*)(trow + tt * 64 + 8 * b + 2 * tg);
            float part[4] = {0.0f, 0.0f, 0.0f, 0.0f};
#pragma unroll
            for (int b = 0; b < 8; b++) {
                part[0] += dA[b][2*rr] * tv[b].x + dA[b][2*rr+1] * tv[b].y;
                part[1] += dA[8+b][2*rr] * tv[b].x + dA[8+b][2*rr+1] * tv[b].y;
                part[2] += dB[b][2*rr] * tv[b].x + dB[b][2*rr+1] * tv[b].y;
                part[3] += dB[8+b][2*rr] * tv[b].x + dB[8+b][2*rr+1] * tv[b].y;
            }
#pragma unroll
            for (int h = 0; h < 4; h++) {
                part[h] += __shfl_xor_sync(0xffffffffu, part[h], 1);
                part[h] += __shfl_xor_sync(0xffffffffu, part[h], 2);
                lg[h][tt] = part[h] + sBias[tt];
            }
        }
        float wn[4][NT];
#pragma unroll
        for (int h = 0; h < 4; h++) {
            float m = fmaxf(fmaxf(lg[h][0], lg[h][1]), fmaxf(lg[h][2], lg[h][3]));
            float den = 0.0f;
#pragma unroll
            for (int tt = 0; tt < NT; tt++) { wn[h][tt] = __expf(lg[h][tt] - m); den += wn[h][tt]; }
            float inv = 1.0f / den;
#pragma unroll
            for (int tt = 0; tt < NT; tt++) wn[h][tt] *= inv;
        }
        float ax[4][8], ay[4][8];
#pragma unroll
        for (int h = 0; h < 4; h++)
#pragma unroll
            for (int b = 0; b < 8; b++) { ax[h][b] = 0.0f; ay[h][b] = 0.0f; }
#pragma unroll
        for (int tt = 0; tt < NT; tt++) {
#pragma unroll
            for (int b = 0; b < 8; b++) {
                float2 tv = *(const float2*)(trow + tt * 64 + 8 * b + 2 * tg);
#pragma unroll
                for (int h = 0; h < 4; h++) {
                    ax[h][b] += wn[h][tt] * tv.x;
                    ay[h][b] += wn[h][tt] * tv.y;
                }
            }
        }
#pragma unroll
        for (int h = 0; h < 4; h++)
#pragma unroll
            for (int b = 0; b < 8; b++)
                tbar[rr][h][b] = packh2(ax[h][b], ay[h][b]);
    }

    CP_WAIT(0);                 // wvo landed
    __syncthreads();            // visibility of all threads' wvo chunks

    // ---- GEMM2: out[128][128] = tbar @ wvo^T, A-frags from registers ----
    float e[16][4];
#pragma unroll
    for (int nt = 0; nt < 16; nt++)
        e[nt][0] = e[nt][1] = e[nt][2] = e[nt][3] = 0.0f;
#pragma unroll
    for (int h = 0; h < 4; h++) {
#pragma unroll
        for (int kp = 0; kp < 4; kp++) {
            int kt = h * 4 + kp;
            uint32_t a0 = tbar[0][h][2*kp],   a2 = tbar[0][h][2*kp+1];
            uint32_t a1 = tbar[1][h][2*kp],   a3 = tbar[1][h][2*kp+1];
#pragma unroll
            for (int np = 0; np < 8; np++) {
                uint32_t b0, b1, b2, b3;
                ldm_x4(b0, b1, b2, b3, bAddr2 + np * (16 * VO_LD * 2) + kt * 32);
                mma16816(e[2 * np],     a0, a1, a2, a3, b0, b1);
                mma16816(e[2 * np + 1], a0, a1, a2, a3, b2, b3);
            }
        }
    }

    // ---- epilogue: add bo, store ----
    {
        float* o0 = outp + (size_t)(p0 + r0 + g) * CZ;
        float* o1 = o0 + 8 * CZ;
#pragma unroll
        for (int nt = 0; nt < 16; nt++) {
            int c0 = nt * 8 + 2 * tg;
            float b0f = sBo[c0], b1f = sBo[c0 + 1];
            *(float2*)(o0 + c0) = make_float2(e[nt][0] + b0f, e[nt][1] + b1f);
            *(float2*)(o1 + c0) = make_float2(e[nt][2] + b0f, e[nt][3] + b1f);
        }
    }
}

extern "C" void kernel_launch(void* const* d_in, const int* in_sizes, int n_in,
                              void* d_out, int out_size)
{
    const float* t     = (const float*)d_in[0];
    const float* z     = (const float*)d_in[1];
    const float* tmask = (const float*)d_in[2];
    const float* wq    = (const float*)d_in[3];
    const float* wk    = (const float*)d_in[4];
    const float* wv    = (const float*)d_in[5];
    const float* wo    = (const float*)d_in[6];
    const float* bo    = (const float*)d_in[7];
    float* outp = (float*)d_out;

    setup_wqk<<<128, 256>>>(wq, wk);
    setup_wvo<<<128, 256>>>(wv, wo);

    cudaFuncSetAttribute(tpa_mma_kernel,
                         cudaFuncAttributeMaxDynamicSharedMemorySize, SMEM_BYTES);
    tpa_mma_kernel<<<PIX / TP, 256, SMEM_BYTES>>>(t, z, tmask, bo, outp);
}